// round 16
// baseline (speedup 1.0000x reference)
#include <cuda_runtime.h>
#include <math.h>

#define N_COLS 4096
#define TPB    256
#define EPS    1e-14f

// R12 config with ONE change: __stwt (write-through) instead of __stcs on
// the output stream. out is written once and never re-read; write-through
// skips L2 line allocation for 256MB of stores, freeing LTS bandwidth for
// the x read stream (LTS aggregate throughput is the binding resource).
//   - v staged to smem during the dot pass; epilogue reads it via LDS
//   - __ldcs on x (single-use), bias on LDG (L1-hot)
//   - ONE barrier; every thread finishes the reduction from broadcast LDS
// out[i] = x[i] - (2*(x.v)/(||v||+eps)^2) * v[i] + bias[i]
__global__ void __launch_bounds__(TPB, 5)
householder_kernel(const float* __restrict__ x,
                   const float* __restrict__ v,
                   const float* __restrict__ bias,
                   float* __restrict__ out) {
    const int tid = threadIdx.x;
    const int w = tid >> 5, l = tid & 31;
    const int row = blockIdx.x;

    const float4* __restrict__ xr = (const float4*)(x + (size_t)row * N_COLS);
    const float4* __restrict__ vr = (const float4*)v;
    const float4* __restrict__ br = (const float4*)bias;
    float4* __restrict__       orow = (float4*)(out + (size_t)row * N_COLS);

    __shared__ float4 vtile[N_COLS / 4];      // 16 KB
    __shared__ float  red_d[TPB / 32];
    __shared__ float  red_n[TPB / 32];

    // ---- single pass: load row + v, stage v to smem, accumulate dots ----
    float4 xv[4];
    float dot = 0.0f, vn = 0.0f;
    #pragma unroll
    for (int j = 0; j < 4; j++) {
        const int idx = tid + j * TPB;        // coalesced 128B per warp
        xv[j] = __ldcs(&xr[idx]);             // streaming: x is single-use
        float4 t = vr[idx];                   // default policy: v is L2-hot
        vtile[idx] = t;                       // STS, drained by the barrier
        dot = fmaf(xv[j].x, t.x, dot);
        dot = fmaf(xv[j].y, t.y, dot);
        dot = fmaf(xv[j].z, t.z, dot);
        dot = fmaf(xv[j].w, t.w, dot);
        vn  = fmaf(t.x, t.x, vn);
        vn  = fmaf(t.y, t.y, vn);
        vn  = fmaf(t.z, t.z, vn);
        vn  = fmaf(t.w, t.w, vn);
    }

    #pragma unroll
    for (int o = 16; o > 0; o >>= 1) {
        dot += __shfl_xor_sync(0xffffffffu, dot, o);
        vn  += __shfl_xor_sync(0xffffffffu, vn,  o);
    }
    if (l == 0) { red_d[w] = dot; red_n[w] = vn; }
    __syncthreads();                           // orders STS + partials

    // every thread finishes the reduction itself (broadcast LDS)
    float td = 0.0f, tn = 0.0f;
    #pragma unroll
    for (int i = 0; i < TPB / 32; i++) { td += red_d[i]; tn += red_n[i]; }
    const float s = 1.0f / (sqrtf(tn) + EPS);
    const float coef = 2.0f * td * s * s;

    // ---- epilogue: v from smem (LDS), bias from L1, write-through store ----
    #pragma unroll
    for (int j = 0; j < 4; j++) {
        const int idx = tid + j * TPB;
        float4 vvj = vtile[idx];               // LDS, conflict-free
        float4 bb  = br[idx];                  // LDG, L1-hot
        float4 o4;
        o4.x = fmaf(-coef, vvj.x, xv[j].x) + bb.x;
        o4.y = fmaf(-coef, vvj.y, xv[j].y) + bb.y;
        o4.z = fmaf(-coef, vvj.z, xv[j].z) + bb.z;
        o4.w = fmaf(-coef, vvj.w, xv[j].w) + bb.w;
        __stwt(&orow[idx], o4);                // write-through: skip L2 alloc
    }
}

extern "C" void kernel_launch(void* const* d_in, const int* in_sizes, int n_in,
                              void* d_out, int out_size) {
    const float* x    = (const float*)d_in[0];   // [16384, 4096]
    const float* v    = (const float*)d_in[1];   // [4096, 1]
    const float* bias = (const float*)d_in[2];   // [4096]
    float* out = (float*)d_out;

    const int n_rows = in_sizes[0] / N_COLS;     // 16384

    householder_kernel<<<n_rows, TPB>>>(x, v, bias, out);
}

// round 17
// speedup vs baseline: 1.0266x; 1.0266x over previous
#include <cuda_runtime.h>
#include <math.h>

#define N_COLS 4096
#define TPB    256
#define EPS    1e-14f

// FINAL (measured optimum across 17 benched configurations, best total
// 80.35us): one 256-thread block per row, 4 float4/thread, fused ||v||^2,
// ONE barrier. At the B300 mixed read/write HBM/LTS ceiling (~6.3 TB/s).
//   - __ldcs on x, __stcs on out: the two single-use 256MB streams get
//     evict-first policy, protecting the v/bias hot lines. (__stwt
//     measured worse: LTS cap is path-independent.)
//   - v staged to smem during the dot pass (STS drained by the barrier),
//     epilogue reads it via LDS -> no epilogue v-LDG in the L1tex queue.
//   - bias stays on the LDG path (L1-hot); staging BOTH v and bias was
//     measured to saturate the smem/L1tex crossbar (90us).
//   - 48 regs -> 5 blocks/SM; higher occupancy configs measured slower
//     (L1tex queue contention), lower ones too (fewer load streams).
// out[i] = x[i] - (2*(x.v)/(||v||+eps)^2) * v[i] + bias[i]
__global__ void __launch_bounds__(TPB, 5)
householder_kernel(const float* __restrict__ x,
                   const float* __restrict__ v,
                   const float* __restrict__ bias,
                   float* __restrict__ out) {
    const int tid = threadIdx.x;
    const int w = tid >> 5, l = tid & 31;
    const int row = blockIdx.x;

    const float4* __restrict__ xr = (const float4*)(x + (size_t)row * N_COLS);
    const float4* __restrict__ vr = (const float4*)v;
    const float4* __restrict__ br = (const float4*)bias;
    float4* __restrict__       orow = (float4*)(out + (size_t)row * N_COLS);

    __shared__ float4 vtile[N_COLS / 4];      // 16 KB
    __shared__ float  red_d[TPB / 32];
    __shared__ float  red_n[TPB / 32];

    // ---- single pass: load row + v, stage v to smem, accumulate dots ----
    float4 xv[4];
    float dot = 0.0f, vn = 0.0f;
    #pragma unroll
    for (int j = 0; j < 4; j++) {
        const int idx = tid + j * TPB;        // coalesced 128B per warp
        xv[j] = __ldcs(&xr[idx]);             // streaming: x is single-use
        float4 t = vr[idx];                   // default policy: v is L2-hot
        vtile[idx] = t;                       // STS, drained by the barrier
        dot = fmaf(xv[j].x, t.x, dot);
        dot = fmaf(xv[j].y, t.y, dot);
        dot = fmaf(xv[j].z, t.z, dot);
        dot = fmaf(xv[j].w, t.w, dot);
        vn  = fmaf(t.x, t.x, vn);
        vn  = fmaf(t.y, t.y, vn);
        vn  = fmaf(t.z, t.z, vn);
        vn  = fmaf(t.w, t.w, vn);
    }

    #pragma unroll
    for (int o = 16; o > 0; o >>= 1) {
        dot += __shfl_xor_sync(0xffffffffu, dot, o);
        vn  += __shfl_xor_sync(0xffffffffu, vn,  o);
    }
    if (l == 0) { red_d[w] = dot; red_n[w] = vn; }
    __syncthreads();                           // orders STS + partials

    // every thread finishes the reduction itself (broadcast LDS)
    float td = 0.0f, tn = 0.0f;
    #pragma unroll
    for (int i = 0; i < TPB / 32; i++) { td += red_d[i]; tn += red_n[i]; }
    const float s = 1.0f / (sqrtf(tn) + EPS);
    const float coef = 2.0f * td * s * s;

    // ---- epilogue: v from smem (LDS), bias from L1, streaming store ----
    #pragma unroll
    for (int j = 0; j < 4; j++) {
        const int idx = tid + j * TPB;
        float4 vvj = vtile[idx];               // LDS, conflict-free
        float4 bb  = br[idx];                  // LDG, L1-hot
        float4 o4;
        o4.x = fmaf(-coef, vvj.x, xv[j].x) + bb.x;
        o4.y = fmaf(-coef, vvj.y, xv[j].y) + bb.y;
        o4.z = fmaf(-coef, vvj.z, xv[j].z) + bb.z;
        o4.w = fmaf(-coef, vvj.w, xv[j].w) + bb.w;
        __stcs(&orow[idx], o4);                // streaming: out never re-read
    }
}

extern "C" void kernel_launch(void* const* d_in, const int* in_sizes, int n_in,
                              void* d_out, int out_size) {
    const float* x    = (const float*)d_in[0];   // [16384, 4096]
    const float* v    = (const float*)d_in[1];   // [4096, 1]
    const float* bias = (const float*)d_in[2];   // [4096]
    float* out = (float*)d_out;

    const int n_rows = in_sizes[0] / N_COLS;     // 16384

    householder_kernel<<<n_rows, TPB>>>(x, v, bias, out);
}